// round 2
// baseline (speedup 1.0000x reference)
#include <cuda_runtime.h>
#include <math.h>

#define IN_DIM   768
#define HID      1024
#define CLIP     512
#define NG       4
#define DS       64
#define DC       4
#define HD       64
#define DIN      2048
#define NH       32
#define CONV_DIM 2560
#define DINP     4640
#define BATCH    1024
#define EPS      1e-5f

// ---------------- scratch (no cudaMalloc allowed) ----------------
__device__ float g_x[BATCH * IN_DIM];        // layernormed input
__device__ float g_t1[BATCH * HID];
__device__ float g_t2[BATCH * HID];
__device__ float g_gated[BATCH * HID];
__device__ float g_zx[BATCH * DINP];
__device__ float g_xbc[BATCH * CONV_DIM];    // post-conv silu activation
__device__ float g_dt[BATCH * NH];
__device__ float g_dA[BATCH * NH];
__device__ float g_y[BATCH * DIN];
__device__ float g_yn[BATCH * DIN];
__device__ float g_tmp[BATCH * HID];
__device__ float g_outpre[BATCH * HID];
__device__ float g_outf[BATCH * HID];

__device__ __forceinline__ float sigmoidf_(float v) { return 1.0f / (1.0f + expf(-v)); }
__device__ __forceinline__ float siluf_(float v)    { return v / (1.0f + expf(-v)); }

// ---------------- layernorm ----------------
__global__ void ln_kernel(const float* __restrict__ ff,
                          const float* __restrict__ w,
                          const float* __restrict__ b,
                          float* __restrict__ out) {
    int row = blockIdx.x;
    const float* in = ff + (size_t)row * IN_DIM;
    float* o = out + (size_t)row * IN_DIM;
    int tid = threadIdx.x;               // 256 threads
    float v0 = in[tid], v1 = in[tid + 256], v2 = in[tid + 512];
    float s = v0 + v1 + v2;
    float s2 = v0 * v0 + v1 * v1 + v2 * v2;
    // warp reduce
    for (int o2 = 16; o2; o2 >>= 1) {
        s  += __shfl_down_sync(0xffffffffu, s,  o2);
        s2 += __shfl_down_sync(0xffffffffu, s2, o2);
    }
    __shared__ float ss[8], ss2[8];
    int wid = tid >> 5, lid = tid & 31;
    if (lid == 0) { ss[wid] = s; ss2[wid] = s2; }
    __syncthreads();
    __shared__ float mu_s, rstd_s;
    if (tid == 0) {
        float ts = 0.f, ts2 = 0.f;
        for (int i = 0; i < 8; i++) { ts += ss[i]; ts2 += ss2[i]; }
        float mu = ts / IN_DIM;
        float var = ts2 / IN_DIM - mu * mu;
        mu_s = mu;
        rstd_s = rsqrtf(var + EPS);
    }
    __syncthreads();
    float mu = mu_s, rstd = rstd_s;
    o[tid]       = (v0 - mu) * rstd * w[tid]       + b[tid];
    o[tid + 256] = (v1 - mu) * rstd * w[tid + 256] + b[tid + 256];
    o[tid + 512] = (v2 - mu) * rstd * w[tid + 512] + b[tid + 512];
}

// ---------------- tiled SGEMM:  C[M,N] = A[M,K] @ W[N,K]^T (+ bias) ----------------
// BM=64, BN=64, BK=16, block 16x16, 4x4 per thread.
__global__ void sgemm_kernel(const float* __restrict__ A,
                             const float* __restrict__ W,
                             const float* __restrict__ bias,
                             float* __restrict__ C,
                             int M, int N, int K) {
    __shared__ __align__(16) float As[16][64];
    __shared__ __align__(16) float Bs[16][64];
    int tx = threadIdx.x, ty = threadIdx.y;
    int t = ty * 16 + tx;                       // 0..255
    int n0 = blockIdx.x * 64;
    int m0 = blockIdx.y * 64;

    int lr = t >> 2;           // 0..63
    int lc = (t & 3) * 4;      // 0,4,8,12

    float acc[4][4];
#pragma unroll
    for (int i = 0; i < 4; i++)
#pragma unroll
        for (int j = 0; j < 4; j++) acc[i][j] = 0.f;

    for (int k0 = 0; k0 < K; k0 += 16) {
        // load A tile (M divisible by 64, K by 16 — no guards)
        float4 av = *(const float4*)(A + (size_t)(m0 + lr) * K + k0 + lc);
        As[lc + 0][lr] = av.x; As[lc + 1][lr] = av.y;
        As[lc + 2][lr] = av.z; As[lc + 3][lr] = av.w;
        // load W tile with N guard
        float4 bv = make_float4(0.f, 0.f, 0.f, 0.f);
        if (n0 + lr < N)
            bv = *(const float4*)(W + (size_t)(n0 + lr) * K + k0 + lc);
        Bs[lc + 0][lr] = bv.x; Bs[lc + 1][lr] = bv.y;
        Bs[lc + 2][lr] = bv.z; Bs[lc + 3][lr] = bv.w;
        __syncthreads();
#pragma unroll
        for (int k = 0; k < 16; k++) {
            float4 a = *(const float4*)&As[k][ty * 4];
            float4 b = *(const float4*)&Bs[k][tx * 4];
            float ar[4] = {a.x, a.y, a.z, a.w};
            float br[4] = {b.x, b.y, b.z, b.w};
#pragma unroll
            for (int i = 0; i < 4; i++)
#pragma unroll
                for (int j = 0; j < 4; j++)
                    acc[i][j] = fmaf(ar[i], br[j], acc[i][j]);
        }
        __syncthreads();
    }

#pragma unroll
    for (int i = 0; i < 4; i++) {
        int m = m0 + ty * 4 + i;
#pragma unroll
        for (int j = 0; j < 4; j++) {
            int n = n0 + tx * 4 + j;
            if (n < N) {
                float v = acc[i][j];
                if (bias) v += bias[n];
                C[(size_t)m * N + n] = v;
            }
        }
    }
}

// ---------------- elementwise ----------------
__global__ void sigmul_kernel(const float* __restrict__ a,
                              const float* __restrict__ b,
                              float* __restrict__ out, int n) {
    int i = blockIdx.x * blockDim.x + threadIdx.x;
    if (i < n) out[i] = a[i] * sigmoidf_(b[i]);
}

__global__ void add_kernel(const float* __restrict__ a,
                           const float* __restrict__ b,
                           float* __restrict__ out, int n) {
    int i = blockIdx.x * blockDim.x + threadIdx.x;
    if (i < n) out[i] = a[i] + b[i];
}

// ---------------- conv shift + depthwise conv + silu ----------------
__global__ void conv_kernel(const float* __restrict__ conv_state,
                            const float* __restrict__ zx,
                            const float* __restrict__ conv_w,
                            const float* __restrict__ conv_b,
                            float* __restrict__ new_conv_out,
                            float* __restrict__ xbc_act) {
    int idx = blockIdx.x * blockDim.x + threadIdx.x;   // b*CONV_DIM + c
    if (idx >= BATCH * CONV_DIM) return;
    int b = idx / CONV_DIM, c = idx - b * CONV_DIM;
    float4 cs = ((const float4*)conv_state)[idx];
    float xn = zx[(size_t)b * DINP + DIN + c];
    float4 w = ((const float4*)conv_w)[c];
    float acc = cs.y * w.x + cs.z * w.y + cs.w * w.z + xn * w.w + conv_b[c];
    xbc_act[idx] = siluf_(acc);
    ((float4*)new_conv_out)[idx] = make_float4(cs.y, cs.z, cs.w, xn);
}

// ---------------- dt softplus + dA ----------------
__global__ void dt_kernel(const float* __restrict__ zx,
                          const float* __restrict__ dt_bias,
                          const float* __restrict__ A_log,
                          float* __restrict__ dt_out,
                          float* __restrict__ dA_out) {
    int idx = blockIdx.x * blockDim.x + threadIdx.x;   // b*NH + h
    if (idx >= BATCH * NH) return;
    int b = idx >> 5, h = idx & 31;
    float raw = zx[(size_t)b * DINP + DIN + CONV_DIM + h] + dt_bias[h];
    float sp = (raw > 20.f) ? raw : log1pf(expf(raw));
    float A = -expf(A_log[h]);
    dt_out[idx] = sp;
    dA_out[idx] = expf(sp * A);
}

// ---------------- SSM state update + C contraction ----------------
// block: (16, 64) — tx indexes n (float4 chunk), ty = p.  one head per block.
__global__ void ssm_kernel(const float* __restrict__ ssm_state,
                           const float* __restrict__ xbc,
                           const float* __restrict__ dt,
                           const float* __restrict__ dA,
                           const float* __restrict__ Dp,
                           float* __restrict__ new_ssm_out,
                           float* __restrict__ y) {
    int bh = blockIdx.x;
    int b = bh >> 5, h = bh & 31, g = h >> 3;
    int tx = threadIdx.x, p = threadIdx.y;

    __shared__ float Bsh[DS], Csh[DS];
    int t = p * 16 + tx;
    if (t < DS)            Bsh[t]       = xbc[(size_t)b * CONV_DIM + DIN + g * DS + t];
    else if (t < 2 * DS)   Csh[t - DS]  = xbc[(size_t)b * CONV_DIM + DIN + NG * DS + g * DS + (t - DS)];
    __syncthreads();

    float x   = xbc[(size_t)b * CONV_DIM + h * HD + p];
    float dtv = dt[bh];
    float dAv = dA[bh];
    float coef = dtv * x;

    size_t base = ((size_t)bh * HD + p) * DS + tx * 4;
    float4 s  = *(const float4*)(ssm_state + base);
    float4 Bv = *(const float4*)&Bsh[tx * 4];
    float4 Cv = *(const float4*)&Csh[tx * 4];
    float4 ns;
    ns.x = fmaf(s.x, dAv, coef * Bv.x);
    ns.y = fmaf(s.y, dAv, coef * Bv.y);
    ns.z = fmaf(s.z, dAv, coef * Bv.z);
    ns.w = fmaf(s.w, dAv, coef * Bv.w);
    *(float4*)(new_ssm_out + base) = ns;

    float part = ns.x * Cv.x + ns.y * Cv.y + ns.z * Cv.z + ns.w * Cv.w;
#pragma unroll
    for (int o = 8; o; o >>= 1)
        part += __shfl_down_sync(0xffffffffu, part, o, 16);
    if (tx == 0)
        y[(size_t)b * DIN + h * HD + p] = part + Dp[h] * x;
}

// ---------------- y gating + grouped RMS norm ----------------
// block: 128 threads, one (batch, group) per block, group = 512 elems, 4/thread.
__global__ void ynorm_kernel(const float* __restrict__ y,
                             const float* __restrict__ zx,
                             const float* __restrict__ norm_w,
                             float* __restrict__ yn) {
    int b = blockIdx.x, g = blockIdx.y;
    int tid = threadIdx.x;
    int idx = g * 512 + tid * 4;
    float4 yv = *(const float4*)(y + (size_t)b * DIN + idx);
    float4 zv = *(const float4*)(zx + (size_t)b * DINP + idx);
    float v[4];
    v[0] = yv.x * siluf_(zv.x);
    v[1] = yv.y * siluf_(zv.y);
    v[2] = yv.z * siluf_(zv.z);
    v[3] = yv.w * siluf_(zv.w);
    float ss = v[0]*v[0] + v[1]*v[1] + v[2]*v[2] + v[3]*v[3];
    for (int o = 16; o; o >>= 1) ss += __shfl_down_sync(0xffffffffu, ss, o);
    __shared__ float wsum[4];
    int wid = tid >> 5, lid = tid & 31;
    if (lid == 0) wsum[wid] = ss;
    __syncthreads();
    __shared__ float scale_s;
    if (tid == 0) {
        float tot = wsum[0] + wsum[1] + wsum[2] + wsum[3];
        scale_s = rsqrtf(tot / 512.f + EPS);
    }
    __syncthreads();
    float sc = scale_s;
    float4 ov;
    ov.x = v[0] * sc * norm_w[idx + 0];
    ov.y = v[1] * sc * norm_w[idx + 1];
    ov.z = v[2] * sc * norm_w[idx + 2];
    ov.w = v[3] * sc * norm_w[idx + 3];
    *(float4*)(yn + (size_t)b * DIN + idx) = ov;
}

// ---------------- launch ----------------
extern "C" void kernel_launch(void* const* d_in, const int* in_sizes, int n_in,
                              void* d_out, int out_size) {
    const float* frame_feat   = (const float*)d_in[0];
    const float* conv_state   = (const float*)d_in[1];
    const float* ssm_state    = (const float*)d_in[2];
    const float* ln_w         = (const float*)d_in[3];
    const float* ln_b         = (const float*)d_in[4];
    const float* w_in_gate    = (const float*)d_in[5];
    const float* b_in_gate    = (const float*)d_in[6];
    const float* w_input_proj = (const float*)d_in[7];
    const float* b_input_proj = (const float*)d_in[8];
    const float* w_in_proj    = (const float*)d_in[9];
    const float* conv_w       = (const float*)d_in[10];
    const float* conv_b       = (const float*)d_in[11];
    const float* A_log        = (const float*)d_in[12];
    const float* Dp           = (const float*)d_in[13];
    const float* dt_bias      = (const float*)d_in[14];
    const float* norm_w       = (const float*)d_in[15];
    const float* w_out_proj   = (const float*)d_in[16];
    const float* w_out_gate   = (const float*)d_in[17];
    const float* b_out_gate   = (const float*)d_in[18];
    const float* w_proj       = (const float*)d_in[19];
    const float* b_proj       = (const float*)d_in[20];

    float* out = (float*)d_out;
    float* out_clip = out;                                   // [1024, 512]
    float* out_conv = out + (size_t)BATCH * CLIP;            // [1024, 2560, 4]
    float* out_ssm  = out_conv + (size_t)BATCH * CONV_DIM * DC; // [1024, 32, 64, 64]

    float *x, *t1, *t2, *gated, *zx, *xbc, *dtv, *dAv, *y, *yn, *tmp, *outpre, *outf;
    cudaGetSymbolAddress((void**)&x,      g_x);
    cudaGetSymbolAddress((void**)&t1,     g_t1);
    cudaGetSymbolAddress((void**)&t2,     g_t2);
    cudaGetSymbolAddress((void**)&gated,  g_gated);
    cudaGetSymbolAddress((void**)&zx,     g_zx);
    cudaGetSymbolAddress((void**)&xbc,    g_xbc);
    cudaGetSymbolAddress((void**)&dtv,    g_dt);
    cudaGetSymbolAddress((void**)&dAv,    g_dA);
    cudaGetSymbolAddress((void**)&y,      g_y);
    cudaGetSymbolAddress((void**)&yn,     g_yn);
    cudaGetSymbolAddress((void**)&tmp,    g_tmp);
    cudaGetSymbolAddress((void**)&outpre, g_outpre);
    cudaGetSymbolAddress((void**)&outf,   g_outf);

    dim3 gblk(16, 16);

    // 1. layernorm
    ln_kernel<<<BATCH, 256>>>(frame_feat, ln_w, ln_b, x);

    // 2-3. input projections
    sgemm_kernel<<<dim3(HID / 64, BATCH / 64), gblk>>>(x, w_input_proj, b_input_proj, t1, BATCH, HID, IN_DIM);
    sgemm_kernel<<<dim3(HID / 64, BATCH / 64), gblk>>>(x, w_in_gate, b_in_gate, t2, BATCH, HID, IN_DIM);

    // 4. gated = t1 * sigmoid(t2)
    sigmul_kernel<<<(BATCH * HID + 255) / 256, 256>>>(t1, t2, gated, BATCH * HID);

    // 5. zxbcdt = gated @ w_in_proj^T
    sgemm_kernel<<<dim3((DINP + 63) / 64, BATCH / 64), gblk>>>(gated, w_in_proj, nullptr, zx, BATCH, DINP, HID);

    // 6. conv shift + depthwise conv + silu (writes new_conv output)
    conv_kernel<<<(BATCH * CONV_DIM + 255) / 256, 256>>>(conv_state, zx, conv_w, conv_b, out_conv, xbc);

    // 7. dt softplus + dA
    dt_kernel<<<(BATCH * NH + 255) / 256, 256>>>(zx, dt_bias, A_log, dtv, dAv);

    // 8. SSM update (writes new_ssm output) + y
    ssm_kernel<<<BATCH * NH, dim3(16, 64)>>>(ssm_state, xbc, dtv, dAv, Dp, out_ssm, y);

    // 9. y gating + grouped rmsnorm
    ynorm_kernel<<<dim3(BATCH, NG), 128>>>(y, zx, norm_w, yn);

    // 10. ssm_out = yn @ w_out_proj^T
    sgemm_kernel<<<dim3(HID / 64, BATCH / 64), gblk>>>(yn, w_out_proj, nullptr, tmp, BATCH, HID, DIN);

    // 11. outpre = ssm_out + gated
    add_kernel<<<(BATCH * HID + 255) / 256, 256>>>(tmp, gated, outpre, BATCH * HID);

    // 12. gate logits = outpre @ w_out_gate^T + b
    sgemm_kernel<<<dim3(HID / 64, BATCH / 64), gblk>>>(outpre, w_out_gate, b_out_gate, tmp, BATCH, HID, HID);

    // 13. outf = outpre * sigmoid(gate logits)
    sigmul_kernel<<<(BATCH * HID + 255) / 256, 256>>>(outpre, tmp, outf, BATCH * HID);

    // 14. clip = outf @ w_proj^T + b
    sgemm_kernel<<<dim3(CLIP / 64, BATCH / 64), gblk>>>(outf, w_proj, b_proj, out_clip, BATCH, CLIP, HID);
}

// round 8
// speedup vs baseline: 1.5241x; 1.5241x over previous
#include <cuda_runtime.h>
#include <math.h>

#define IN_DIM   768
#define HID      1024
#define CLIP     512
#define NG       4
#define DS       64
#define DC       4
#define HD       64
#define DIN      2048
#define NH       32
#define CONV_DIM 2560
#define DINP     4640
#define BATCH    1024
#define EPS      1e-5f

// ---------------- scratch (no cudaMalloc allowed) ----------------
__device__ float g_x[BATCH * IN_DIM];
__device__ float g_t1[BATCH * HID];
__device__ float g_gated[BATCH * HID];
__device__ float g_zx[BATCH * DINP];
__device__ float g_xbc[BATCH * CONV_DIM];
__device__ float g_dt[BATCH * NH];
__device__ float g_dA[BATCH * NH];
__device__ float g_y[BATCH * DIN];
__device__ float g_yn[BATCH * DIN];
__device__ float g_outpre[BATCH * HID];
__device__ float g_outf[BATCH * HID];

__device__ __forceinline__ float sigmoidf_(float v) { return 1.0f / (1.0f + expf(-v)); }
__device__ __forceinline__ float siluf_(float v)    { return v / (1.0f + expf(-v)); }

__device__ __forceinline__ unsigned f2tf32(float x) {
    unsigned r;
    asm("cvt.rna.tf32.f32 %0, %1;" : "=r"(r) : "f"(x));
    return r;
}

// ---------------- layernorm ----------------
__global__ void ln_kernel(const float* __restrict__ ff,
                          const float* __restrict__ w,
                          const float* __restrict__ b,
                          float* __restrict__ out) {
    int row = blockIdx.x;
    const float* in = ff + (size_t)row * IN_DIM;
    float* o = out + (size_t)row * IN_DIM;
    int tid = threadIdx.x;               // 256 threads
    float v0 = in[tid], v1 = in[tid + 256], v2 = in[tid + 512];
    float s = v0 + v1 + v2;
    float s2 = v0 * v0 + v1 * v1 + v2 * v2;
    for (int o2 = 16; o2; o2 >>= 1) {
        s  += __shfl_down_sync(0xffffffffu, s,  o2);
        s2 += __shfl_down_sync(0xffffffffu, s2, o2);
    }
    __shared__ float ss[8], ss2[8];
    int wid = tid >> 5, lid = tid & 31;
    if (lid == 0) { ss[wid] = s; ss2[wid] = s2; }
    __syncthreads();
    __shared__ float mu_s, rstd_s;
    if (tid == 0) {
        float ts = 0.f, ts2 = 0.f;
        for (int i = 0; i < 8; i++) { ts += ss[i]; ts2 += ss2[i]; }
        float mu = ts / IN_DIM;
        float var = ts2 / IN_DIM - mu * mu;
        mu_s = mu;
        rstd_s = rsqrtf(var + EPS);
    }
    __syncthreads();
    float mu = mu_s, rstd = rstd_s;
    o[tid]       = (v0 - mu) * rstd * w[tid]       + b[tid];
    o[tid + 256] = (v1 - mu) * rstd * w[tid + 256] + b[tid + 256];
    o[tid + 512] = (v2 - mu) * rstd * w[tid + 512] + b[tid + 512];
}

// ---------------- TF32 tensor-core GEMM ----------------
// C[M,N] = A[M,K] @ W[N,K]^T (+ bias) with fused epilogue.
//   mode 0: C = acc (+bias)
//   mode 1: C = other * sigmoid(acc (+bias))
//   mode 2: C = acc + other
// Block: BM x 128, BK=32, 256 threads = 8 warps (2 M x 4 N),
// warp tile (BM/2) x 32, mma m16n8k8 tf32.
template<int BM>
__global__ __launch_bounds__(256)
void tf32_gemm(const float* __restrict__ A, const float* __restrict__ W,
               const float* __restrict__ bias, const float* __restrict__ other,
               float* __restrict__ C, int M, int N, int K, int mode)
{
    constexpr int BN = 128;
    constexpr int BK = 32;
    constexpr int MT = BM / 32;   // m16-tiles per warp

    __shared__ unsigned As[BM][36];
    __shared__ unsigned Bs[BN][36];

    int tid  = threadIdx.x;
    int warp = tid >> 5, lane = tid & 31;
    int g    = lane >> 2, tig = lane & 3;
    int wm   = (warp >> 2) * (MT * 16);
    int wn   = (warp & 3) * 32;
    int m0   = blockIdx.y * BM;
    int n0   = blockIdx.x * BN;

    float acc[MT][4][4];
#pragma unroll
    for (int i = 0; i < MT; i++)
#pragma unroll
        for (int j = 0; j < 4; j++)
#pragma unroll
            for (int c = 0; c < 4; c++) acc[i][j][c] = 0.f;

    int lrow = tid >> 3;          // 0..31
    int lcol = (tid & 7) * 4;     // 0,4,...,28

    for (int k0 = 0; k0 < K; k0 += BK) {
        // A tile: BM x 32 (M divisible by BM, K by 32 — no guards)
#pragma unroll
        for (int p = 0; p < BM / 32; p++) {
            int r = p * 32 + lrow;
            float4 v = *(const float4*)(A + (size_t)(m0 + r) * K + k0 + lcol);
            uint4 u = make_uint4(f2tf32(v.x), f2tf32(v.y), f2tf32(v.z), f2tf32(v.w));
            *(uint4*)&As[r][lcol] = u;
        }
        // W tile: 128 x 32 with N guard
#pragma unroll
        for (int p = 0; p < 4; p++) {
            int r = p * 32 + lrow;
            float4 v = make_float4(0.f, 0.f, 0.f, 0.f);
            if (n0 + r < N)
                v = *(const float4*)(W + (size_t)(n0 + r) * K + k0 + lcol);
            uint4 u = make_uint4(f2tf32(v.x), f2tf32(v.y), f2tf32(v.z), f2tf32(v.w));
            *(uint4*)&Bs[r][lcol] = u;
        }
        __syncthreads();

#pragma unroll
        for (int k8 = 0; k8 < 4; k8++) {
            int kb = k8 * 8;
            unsigned a[MT][4], b[4][2];
#pragma unroll
            for (int mt = 0; mt < MT; mt++) {
                int m = wm + mt * 16;
                a[mt][0] = As[m + g][kb + tig];
                a[mt][1] = As[m + g + 8][kb + tig];
                a[mt][2] = As[m + g][kb + tig + 4];
                a[mt][3] = As[m + g + 8][kb + tig + 4];
            }
#pragma unroll
            for (int nt = 0; nt < 4; nt++) {
                int n = wn + nt * 8;
                b[nt][0] = Bs[n + g][kb + tig];
                b[nt][1] = Bs[n + g][kb + tig + 4];
            }
#pragma unroll
            for (int mt = 0; mt < MT; mt++)
#pragma unroll
                for (int nt = 0; nt < 4; nt++) {
                    asm volatile(
                        "mma.sync.aligned.m16n8k8.row.col.f32.tf32.tf32.f32 "
                        "{%0,%1,%2,%3}, {%4,%5,%6,%7}, {%8,%9}, {%0,%1,%2,%3};\n"
                        : "+f"(acc[mt][nt][0]), "+f"(acc[mt][nt][1]),
                          "+f"(acc[mt][nt][2]), "+f"(acc[mt][nt][3])
                        : "r"(a[mt][0]), "r"(a[mt][1]), "r"(a[mt][2]), "r"(a[mt][3]),
                          "r"(b[nt][0]), "r"(b[nt][1]));
                }
        }
        __syncthreads();
    }

    // epilogue
#pragma unroll
    for (int mt = 0; mt < MT; mt++) {
#pragma unroll
        for (int nt = 0; nt < 4; nt++) {
            int ng = n0 + wn + nt * 8 + 2 * tig;
            if (ng >= N) continue;
#pragma unroll
            for (int half = 0; half < 2; half++) {
                int mg = m0 + wm + mt * 16 + g + half * 8;
                float v0 = acc[mt][nt][half * 2 + 0];
                float v1 = acc[mt][nt][half * 2 + 1];
                if (bias) { v0 += bias[ng]; v1 += bias[ng + 1]; }
                size_t off = (size_t)mg * N + ng;
                if (mode == 1) {
                    v0 = other[off]     * sigmoidf_(v0);
                    v1 = other[off + 1] * sigmoidf_(v1);
                } else if (mode == 2) {
                    v0 += other[off];
                    v1 += other[off + 1];
                }
                *(float2*)(C + off) = make_float2(v0, v1);
            }
        }
    }
}

// ---------------- conv shift + depthwise conv + silu ----------------
__global__ void conv_kernel(const float* __restrict__ conv_state,
                            const float* __restrict__ zx,
                            const float* __restrict__ conv_w,
                            const float* __restrict__ conv_b,
                            float* __restrict__ new_conv_out,
                            float* __restrict__ xbc_act) {
    int idx = blockIdx.x * blockDim.x + threadIdx.x;   // b*CONV_DIM + c
    if (idx >= BATCH * CONV_DIM) return;
    int b = idx / CONV_DIM, c = idx - b * CONV_DIM;
    float4 cs = ((const float4*)conv_state)[idx];
    float xn = zx[(size_t)b * DINP + DIN + c];
    float4 w = ((const float4*)conv_w)[c];
    float acc = cs.y * w.x + cs.z * w.y + cs.w * w.z + xn * w.w + conv_b[c];
    xbc_act[idx] = siluf_(acc);
    ((float4*)new_conv_out)[idx] = make_float4(cs.y, cs.z, cs.w, xn);
}

// ---------------- dt softplus + dA ----------------
__global__ void dt_kernel(const float* __restrict__ zx,
                          const float* __restrict__ dt_bias,
                          const float* __restrict__ A_log,
                          float* __restrict__ dt_out,
                          float* __restrict__ dA_out) {
    int idx = blockIdx.x * blockDim.x + threadIdx.x;   // b*NH + h
    if (idx >= BATCH * NH) return;
    int b = idx >> 5, h = idx & 31;
    float raw = zx[(size_t)b * DINP + DIN + CONV_DIM + h] + dt_bias[h];
    float sp = (raw > 20.f) ? raw : log1pf(expf(raw));
    float A = -expf(A_log[h]);
    dt_out[idx] = sp;
    dA_out[idx] = expf(sp * A);
}

// ---------------- SSM state update + C contraction ----------------
__global__ void ssm_kernel(const float* __restrict__ ssm_state,
                           const float* __restrict__ xbc,
                           const float* __restrict__ dt,
                           const float* __restrict__ dA,
                           const float* __restrict__ Dp,
                           float* __restrict__ new_ssm_out,
                           float* __restrict__ y) {
    int bh = blockIdx.x;
    int b = bh >> 5, h = bh & 31, g = h >> 3;
    int tx = threadIdx.x, p = threadIdx.y;

    __shared__ float Bsh[DS], Csh[DS];
    int t = p * 16 + tx;
    if (t < DS)            Bsh[t]       = xbc[(size_t)b * CONV_DIM + DIN + g * DS + t];
    else if (t < 2 * DS)   Csh[t - DS]  = xbc[(size_t)b * CONV_DIM + DIN + NG * DS + g * DS + (t - DS)];
    __syncthreads();

    float x   = xbc[(size_t)b * CONV_DIM + h * HD + p];
    float dtv = dt[bh];
    float dAv = dA[bh];
    float coef = dtv * x;

    size_t base = ((size_t)bh * HD + p) * DS + tx * 4;
    float4 s  = *(const float4*)(ssm_state + base);
    float4 Bv = *(const float4*)&Bsh[tx * 4];
    float4 Cv = *(const float4*)&Csh[tx * 4];
    float4 ns;
    ns.x = fmaf(s.x, dAv, coef * Bv.x);
    ns.y = fmaf(s.y, dAv, coef * Bv.y);
    ns.z = fmaf(s.z, dAv, coef * Bv.z);
    ns.w = fmaf(s.w, dAv, coef * Bv.w);
    *(float4*)(new_ssm_out + base) = ns;

    float part = ns.x * Cv.x + ns.y * Cv.y + ns.z * Cv.z + ns.w * Cv.w;
#pragma unroll
    for (int o = 8; o; o >>= 1)
        part += __shfl_down_sync(0xffffffffu, part, o, 16);
    if (tx == 0)
        y[(size_t)b * DIN + h * HD + p] = part + Dp[h] * x;
}

// ---------------- y gating + grouped RMS norm ----------------
__global__ void ynorm_kernel(const float* __restrict__ y,
                             const float* __restrict__ zx,
                             const float* __restrict__ norm_w,
                             float* __restrict__ yn) {
    int b = blockIdx.x, g = blockIdx.y;
    int tid = threadIdx.x;
    int idx = g * 512 + tid * 4;
    float4 yv = *(const float4*)(y + (size_t)b * DIN + idx);
    float4 zv = *(const float4*)(zx + (size_t)b * DINP + idx);
    float v[4];
    v[0] = yv.x * siluf_(zv.x);
    v[1] = yv.y * siluf_(zv.y);
    v[2] = yv.z * siluf_(zv.z);
    v[3] = yv.w * siluf_(zv.w);
    float ss = v[0]*v[0] + v[1]*v[1] + v[2]*v[2] + v[3]*v[3];
    for (int o = 16; o; o >>= 1) ss += __shfl_down_sync(0xffffffffu, ss, o);
    __shared__ float wsum[4];
    int wid = tid >> 5, lid = tid & 31;
    if (lid == 0) wsum[wid] = ss;
    __syncthreads();
    __shared__ float scale_s;
    if (tid == 0) {
        float tot = wsum[0] + wsum[1] + wsum[2] + wsum[3];
        scale_s = rsqrtf(tot / 512.f + EPS);
    }
    __syncthreads();
    float sc = scale_s;
    float4 ov;
    ov.x = v[0] * sc * norm_w[idx + 0];
    ov.y = v[1] * sc * norm_w[idx + 1];
    ov.z = v[2] * sc * norm_w[idx + 2];
    ov.w = v[3] * sc * norm_w[idx + 3];
    *(float4*)(yn + (size_t)b * DIN + idx) = ov;
}

// ---------------- launch ----------------
extern "C" void kernel_launch(void* const* d_in, const int* in_sizes, int n_in,
                              void* d_out, int out_size) {
    const float* frame_feat   = (const float*)d_in[0];
    const float* conv_state   = (const float*)d_in[1];
    const float* ssm_state    = (const float*)d_in[2];
    const float* ln_w         = (const float*)d_in[3];
    const float* ln_b         = (const float*)d_in[4];
    const float* w_in_gate    = (const float*)d_in[5];
    const float* b_in_gate    = (const float*)d_in[6];
    const float* w_input_proj = (const float*)d_in[7];
    const float* b_input_proj = (const float*)d_in[8];
    const float* w_in_proj    = (const float*)d_in[9];
    const float* conv_w       = (const float*)d_in[10];
    const float* conv_b       = (const float*)d_in[11];
    const float* A_log        = (const float*)d_in[12];
    const float* Dp           = (const float*)d_in[13];
    const float* dt_bias      = (const float*)d_in[14];
    const float* norm_w       = (const float*)d_in[15];
    const float* w_out_proj   = (const float*)d_in[16];
    const float* w_out_gate   = (const float*)d_in[17];
    const float* b_out_gate   = (const float*)d_in[18];
    const float* w_proj       = (const float*)d_in[19];
    const float* b_proj       = (const float*)d_in[20];

    float* out = (float*)d_out;
    float* out_clip = out;                                      // [1024, 512]
    float* out_conv = out + (size_t)BATCH * CLIP;               // [1024, 2560, 4]
    float* out_ssm  = out_conv + (size_t)BATCH * CONV_DIM * DC; // [1024, 32, 64, 64]

    float *x, *t1, *gated, *zx, *xbc, *dtv, *dAv, *y, *yn, *outpre, *outf;
    cudaGetSymbolAddress((void**)&x,      g_x);
    cudaGetSymbolAddress((void**)&t1,     g_t1);
    cudaGetSymbolAddress((void**)&gated,  g_gated);
    cudaGetSymbolAddress((void**)&zx,     g_zx);
    cudaGetSymbolAddress((void**)&xbc,    g_xbc);
    cudaGetSymbolAddress((void**)&dtv,    g_dt);
    cudaGetSymbolAddress((void**)&dAv,    g_dA);
    cudaGetSymbolAddress((void**)&y,      g_y);
    cudaGetSymbolAddress((void**)&yn,     g_yn);
    cudaGetSymbolAddress((void**)&outpre, g_outpre);
    cudaGetSymbolAddress((void**)&outf,   g_outf);

    // 1. layernorm
    ln_kernel<<<BATCH, 256>>>(frame_feat, ln_w, ln_b, x);

    // 2. t1 = x @ w_input_proj^T + b
    tf32_gemm<64><<<dim3(HID / 128, BATCH / 64), 256>>>(
        x, w_input_proj, b_input_proj, nullptr, t1, BATCH, HID, IN_DIM, 0);

    // 3. gated = t1 * sigmoid(x @ w_in_gate^T + b)   (fused epilogue)
    tf32_gemm<64><<<dim3(HID / 128, BATCH / 64), 256>>>(
        x, w_in_gate, b_in_gate, t1, gated, BATCH, HID, IN_DIM, 1);

    // 4. zxbcdt = gated @ w_in_proj^T
    tf32_gemm<128><<<dim3((DINP + 127) / 128, BATCH / 128), 256>>>(
        gated, w_in_proj, nullptr, nullptr, zx, BATCH, DINP, HID, 0);

    // 5. conv shift + depthwise conv + silu (writes new_conv output)
    conv_kernel<<<(BATCH * CONV_DIM + 255) / 256, 256>>>(conv_state, zx, conv_w, conv_b, out_conv, xbc);

    // 6. dt softplus + dA
    dt_kernel<<<(BATCH * NH + 255) / 256, 256>>>(zx, dt_bias, A_log, dtv, dAv);

    // 7. SSM update (writes new_ssm output) + y
    ssm_kernel<<<BATCH * NH, dim3(16, 64)>>>(ssm_state, xbc, dtv, dAv, Dp, out_ssm, y);

    // 8. y gating + grouped rmsnorm
    ynorm_kernel<<<dim3(BATCH, NG), 128>>>(y, zx, norm_w, yn);

    // 9. outpre = yn @ w_out_proj^T + gated   (fused add)
    tf32_gemm<64><<<dim3(HID / 128, BATCH / 64), 256>>>(
        yn, w_out_proj, nullptr, gated, outpre, BATCH, HID, DIN, 2);

    // 10. outf = outpre * sigmoid(outpre @ w_out_gate^T + b)  (fused)
    tf32_gemm<64><<<dim3(HID / 128, BATCH / 64), 256>>>(
        outpre, w_out_gate, b_out_gate, outpre, outf, BATCH, HID, HID, 1);

    // 11. clip = outf @ w_proj^T + b
    tf32_gemm<64><<<dim3(CLIP / 128, BATCH / 64), 256>>>(
        outf, w_proj, b_proj, nullptr, out_clip, BATCH, CLIP, HID, 0);
}

// round 13
// speedup vs baseline: 1.9759x; 1.2965x over previous
#include <cuda_runtime.h>
#include <math.h>
#include <stdint.h>

#define IN_DIM   768
#define HID      1024
#define CLIP     512
#define NG       4
#define DS       64
#define DC       4
#define HD       64
#define DIN      2048
#define NH       32
#define CONV_DIM 2560
#define DINP     4640
#define BATCH    1024
#define EPS      1e-5f

// ---------------- scratch ----------------
__device__ float g_x[BATCH * IN_DIM];
__device__ float g_t1[BATCH * HID];
__device__ float g_gated[BATCH * HID];
__device__ float g_zx[BATCH * DINP];
__device__ float g_xbc[BATCH * CONV_DIM];
__device__ float g_yn[BATCH * DIN];
__device__ float g_outpre[BATCH * HID];
__device__ float g_outf[BATCH * HID];

__device__ __forceinline__ float sigmoidf_(float v) { return 1.0f / (1.0f + expf(-v)); }
__device__ __forceinline__ float siluf_(float v)    { return v / (1.0f + expf(-v)); }

__device__ __forceinline__ unsigned f2tf32(float x) {
    unsigned r;
    asm("cvt.rna.tf32.f32 %0, %1;" : "=r"(r) : "f"(x));
    return r;
}

__device__ __forceinline__ void cp_async16(uint32_t dst, const void* src, int src_bytes) {
    asm volatile("cp.async.cg.shared.global [%0], [%1], 16, %2;\n"
                 :: "r"(dst), "l"(src), "r"(src_bytes));
}
__device__ __forceinline__ void cp_commit() {
    asm volatile("cp.async.commit_group;\n");
}
template<int N>
__device__ __forceinline__ void cp_wait() {
    asm volatile("cp.async.wait_group %0;\n" :: "n"(N));
}

// ---------------- layernorm ----------------
__global__ void ln_kernel(const float* __restrict__ ff,
                          const float* __restrict__ w,
                          const float* __restrict__ b,
                          float* __restrict__ out) {
    int row = blockIdx.x;
    const float* in = ff + (size_t)row * IN_DIM;
    float* o = out + (size_t)row * IN_DIM;
    int tid = threadIdx.x;               // 256 threads
    float v0 = in[tid], v1 = in[tid + 256], v2 = in[tid + 512];
    float s = v0 + v1 + v2;
    float s2 = v0 * v0 + v1 * v1 + v2 * v2;
    for (int o2 = 16; o2; o2 >>= 1) {
        s  += __shfl_down_sync(0xffffffffu, s,  o2);
        s2 += __shfl_down_sync(0xffffffffu, s2, o2);
    }
    __shared__ float ss[8], ss2[8];
    int wid = tid >> 5, lid = tid & 31;
    if (lid == 0) { ss[wid] = s; ss2[wid] = s2; }
    __syncthreads();
    __shared__ float mu_s, rstd_s;
    if (tid == 0) {
        float ts = 0.f, ts2 = 0.f;
        for (int i = 0; i < 8; i++) { ts += ss[i]; ts2 += ss2[i]; }
        float mu = ts / IN_DIM;
        float var = ts2 / IN_DIM - mu * mu;
        mu_s = mu;
        rstd_s = rsqrtf(var + EPS);
    }
    __syncthreads();
    float mu = mu_s, rstd = rstd_s;
    o[tid]       = (v0 - mu) * rstd * w[tid]       + b[tid];
    o[tid + 256] = (v1 - mu) * rstd * w[tid + 256] + b[tid + 256];
    o[tid + 512] = (v2 - mu) * rstd * w[tid + 512] + b[tid + 512];
}

// ---------------- TF32 tensor-core GEMM, cp.async double-buffered ----------------
// C[M,N] = A[M,K] @ W[N,K]^T (+ bias), epilogue modes:
//   0: C = acc(+bias)   1: C = other * sigmoid(acc(+bias))   2: C = acc + other
// Block BM x 128, BK=32, 256 threads (8 warps 2x4), warp tile (BM/2) x 32.
template<int BM>
__global__ __launch_bounds__(256)
void tf32_gemm(const float* __restrict__ A, const float* __restrict__ W,
               const float* __restrict__ bias, const float* __restrict__ other,
               float* __restrict__ C, int M, int N, int K, int mode)
{
    constexpr int BN = 128;
    constexpr int BK = 32;
    constexpr int MT = BM / 32;
    constexpr int PITCH = 36;                    // floats; 144B rows, 16B aligned, conflict-free
    constexpr int STAGE = (BM + BN) * PITCH;     // floats per stage

    extern __shared__ float smem[];

    int tid  = threadIdx.x;
    int warp = tid >> 5, lane = tid & 31;
    int g    = lane >> 2, tig = lane & 3;
    int wm   = (warp >> 2) * (MT * 16);
    int wn   = (warp & 3) * 32;
    int m0   = blockIdx.y * BM;
    int n0   = blockIdx.x * BN;

    int lrow = tid >> 3;          // 0..31
    int lcol = (tid & 7) * 4;     // 0,4,...,28

    float acc[MT][4][4];
#pragma unroll
    for (int i = 0; i < MT; i++)
#pragma unroll
        for (int j = 0; j < 4; j++)
#pragma unroll
            for (int c = 0; c < 4; c++) acc[i][j][c] = 0.f;

    const int niter = K / BK;

    auto issue = [&](int it, int buf) {
        int k0 = it * BK;
        float* sa = smem + buf * STAGE;
        float* sb = sa + BM * PITCH;
#pragma unroll
        for (int p = 0; p < BM / 32; p++) {
            int r = p * 32 + lrow;
            uint32_t dst = (uint32_t)__cvta_generic_to_shared(sa + r * PITCH + lcol);
            cp_async16(dst, A + (size_t)(m0 + r) * K + k0 + lcol, 16);
        }
#pragma unroll
        for (int p = 0; p < 4; p++) {
            int r = p * 32 + lrow;
            int gn = n0 + r;
            uint32_t dst = (uint32_t)__cvta_generic_to_shared(sb + r * PITCH + lcol);
            const float* src = W + (size_t)(gn < N ? gn : (N - 1)) * K + k0 + lcol;
            cp_async16(dst, src, gn < N ? 16 : 0);   // src-size 0 => zero-fill
        }
    };

    issue(0, 0);
    cp_commit();

    for (int it = 0; it < niter; ++it) {
        int buf = it & 1;
        if (it + 1 < niter) {
            issue(it + 1, buf ^ 1);
            cp_commit();
            cp_wait<1>();
        } else {
            cp_wait<0>();
        }
        __syncthreads();

        const float* sa = smem + buf * STAGE;
        const float* sb = sa + BM * PITCH;

#pragma unroll
        for (int k8 = 0; k8 < 4; k8++) {
            int kb = k8 * 8;
            unsigned a[MT][4], b[4][2];
#pragma unroll
            for (int mt = 0; mt < MT; mt++) {
                int m = wm + mt * 16;
                a[mt][0] = f2tf32(sa[(m + g) * PITCH + kb + tig]);
                a[mt][1] = f2tf32(sa[(m + g + 8) * PITCH + kb + tig]);
                a[mt][2] = f2tf32(sa[(m + g) * PITCH + kb + tig + 4]);
                a[mt][3] = f2tf32(sa[(m + g + 8) * PITCH + kb + tig + 4]);
            }
#pragma unroll
            for (int nt = 0; nt < 4; nt++) {
                int n = wn + nt * 8;
                b[nt][0] = f2tf32(sb[(n + g) * PITCH + kb + tig]);
                b[nt][1] = f2tf32(sb[(n + g) * PITCH + kb + tig + 4]);
            }
#pragma unroll
            for (int mt = 0; mt < MT; mt++)
#pragma unroll
                for (int nt = 0; nt < 4; nt++) {
                    asm volatile(
                        "mma.sync.aligned.m16n8k8.row.col.f32.tf32.tf32.f32 "
                        "{%0,%1,%2,%3}, {%4,%5,%6,%7}, {%8,%9}, {%0,%1,%2,%3};\n"
                        : "+f"(acc[mt][nt][0]), "+f"(acc[mt][nt][1]),
                          "+f"(acc[mt][nt][2]), "+f"(acc[mt][nt][3])
                        : "r"(a[mt][0]), "r"(a[mt][1]), "r"(a[mt][2]), "r"(a[mt][3]),
                          "r"(b[nt][0]), "r"(b[nt][1]));
                }
        }
        __syncthreads();
    }

    // epilogue
#pragma unroll
    for (int mt = 0; mt < MT; mt++) {
#pragma unroll
        for (int nt = 0; nt < 4; nt++) {
            int ng = n0 + wn + nt * 8 + 2 * tig;
            if (ng >= N) continue;
#pragma unroll
            for (int half = 0; half < 2; half++) {
                int mg = m0 + wm + mt * 16 + g + half * 8;
                float v0 = acc[mt][nt][half * 2 + 0];
                float v1 = acc[mt][nt][half * 2 + 1];
                if (bias) { v0 += bias[ng]; v1 += bias[ng + 1]; }
                size_t off = (size_t)mg * N + ng;
                if (mode == 1) {
                    v0 = other[off]     * sigmoidf_(v0);
                    v1 = other[off + 1] * sigmoidf_(v1);
                } else if (mode == 2) {
                    v0 += other[off];
                    v1 += other[off + 1];
                }
                *(float2*)(C + off) = make_float2(v0, v1);
            }
        }
    }
}

// ---------------- conv shift + depthwise conv + silu ----------------
__global__ void conv_kernel(const float* __restrict__ conv_state,
                            const float* __restrict__ zx,
                            const float* __restrict__ conv_w,
                            const float* __restrict__ conv_b,
                            float* __restrict__ new_conv_out,
                            float* __restrict__ xbc_act) {
    int idx = blockIdx.x * blockDim.x + threadIdx.x;   // b*CONV_DIM + c
    if (idx >= BATCH * CONV_DIM) return;
    int b = idx / CONV_DIM, c = idx - b * CONV_DIM;
    float4 cs = ((const float4*)conv_state)[idx];
    float xn = zx[(size_t)b * DINP + DIN + c];
    float4 w = ((const float4*)conv_w)[c];
    float acc = cs.y * w.x + cs.z * w.y + cs.w * w.z + xn * w.w + conv_b[c];
    xbc_act[idx] = siluf_(acc);
    ((float4*)new_conv_out)[idx] = make_float4(cs.y, cs.z, cs.w, xn);
}

// ---------------- fused: dt + SSM state update + C contraction + silu(z) gate + group RMS norm ----------------
// One block per (batch, group): 8 heads x 64 p x 64 n.  512 threads.
// Thread layout: h_loc = tid/64; within head: tn = t64%16 (n float4 chunk), pg = t64/16 (16 p's each).
__global__ __launch_bounds__(512)
void ssm_fused(const float* __restrict__ ssm_state,
               const float* __restrict__ zx,
               const float* __restrict__ xbc,
               const float* __restrict__ A_log,
               const float* __restrict__ Dp,
               const float* __restrict__ dt_bias,
               const float* __restrict__ norm_w,
               float* __restrict__ new_ssm_out,
               float* __restrict__ yn) {
    int bg = blockIdx.x;
    int b = bg >> 2, g = bg & 3;
    int tid = threadIdx.x;
    int h_loc = tid >> 6;
    int t64 = tid & 63;
    int tn = t64 & 15;
    int pg = t64 >> 4;
    int h = g * 8 + h_loc;

    __shared__ float Bsh[DS], Csh[DS], Xsh[512], Zsh[512], Yv[512];
    __shared__ float dtsh[8], dAsh[8], Dpsh[8];

    if (tid < DS)
        Bsh[tid] = xbc[(size_t)b * CONV_DIM + DIN + g * DS + tid];
    else if (tid < 2 * DS)
        Csh[tid - DS] = xbc[(size_t)b * CONV_DIM + DIN + NG * DS + g * DS + (tid - DS)];
    Xsh[tid] = xbc[(size_t)b * CONV_DIM + g * 512 + tid];
    Zsh[tid] = zx[(size_t)b * DINP + g * 512 + tid];
    if (tid < 8) {
        int hh = g * 8 + tid;
        float raw = zx[(size_t)b * DINP + DIN + CONV_DIM + hh] + dt_bias[hh];
        float sp = (raw > 20.f) ? raw : log1pf(expf(raw));
        dtsh[tid] = sp;
        dAsh[tid] = expf(sp * -expf(A_log[hh]));
        Dpsh[tid] = Dp[hh];
    }
    __syncthreads();

    float4 B4 = *(const float4*)&Bsh[tn * 4];
    float4 C4 = *(const float4*)&Csh[tn * 4];
    float dtv = dtsh[h_loc], dAv = dAsh[h_loc];

    size_t head_base = (((size_t)b * NH + h) * HD) * DS;

    float part[16];
#pragma unroll
    for (int i = 0; i < 16; i++) {
        int p = pg * 16 + i;
        size_t off = head_base + (size_t)p * DS + tn * 4;
        float4 s = *(const float4*)(ssm_state + off);
        float coef = dtv * Xsh[h_loc * 64 + p];
        float4 ns;
        ns.x = fmaf(s.x, dAv, coef * B4.x);
        ns.y = fmaf(s.y, dAv, coef * B4.y);
        ns.z = fmaf(s.z, dAv, coef * B4.z);
        ns.w = fmaf(s.w, dAv, coef * B4.w);
        *(float4*)(new_ssm_out + off) = ns;
        part[i] = ns.x * C4.x + ns.y * C4.y + ns.z * C4.z + ns.w * C4.w;
    }

#pragma unroll
    for (int i = 0; i < 16; i++) {
        float v = part[i];
        v += __shfl_down_sync(0xffffffffu, v, 8, 16);
        v += __shfl_down_sync(0xffffffffu, v, 4, 16);
        v += __shfl_down_sync(0xffffffffu, v, 2, 16);
        v += __shfl_down_sync(0xffffffffu, v, 1, 16);
        part[i] = v;
    }
    if (tn == 0) {
        float dp = Dpsh[h_loc];
#pragma unroll
        for (int i = 0; i < 16; i++) {
            int p = pg * 16 + i;
            float x = Xsh[h_loc * 64 + p];
            float y = part[i] + dp * x;
            float z = Zsh[h_loc * 64 + p];
            Yv[h_loc * 64 + p] = y * siluf_(z);
        }
    }
    __syncthreads();

    // group RMS over the 512 values
    float v = Yv[tid];
    float ss = v * v;
    for (int o = 16; o; o >>= 1) ss += __shfl_down_sync(0xffffffffu, ss, o);
    __shared__ float wsums[16];
    int wid = tid >> 5, lid = tid & 31;
    if (lid == 0) wsums[wid] = ss;
    __syncthreads();
    __shared__ float scale_s;
    if (tid == 0) {
        float tot = 0.f;
        for (int i = 0; i < 16; i++) tot += wsums[i];
        scale_s = rsqrtf(tot / 512.f + EPS);
    }
    __syncthreads();
    yn[(size_t)b * DIN + g * 512 + tid] = v * scale_s * norm_w[g * 512 + tid];
}

// ---------------- launch ----------------
extern "C" void kernel_launch(void* const* d_in, const int* in_sizes, int n_in,
                              void* d_out, int out_size) {
    const float* frame_feat   = (const float*)d_in[0];
    const float* conv_state   = (const float*)d_in[1];
    const float* ssm_state    = (const float*)d_in[2];
    const float* ln_w         = (const float*)d_in[3];
    const float* ln_b         = (const float*)d_in[4];
    const float* w_in_gate    = (const float*)d_in[5];
    const float* b_in_gate    = (const float*)d_in[6];
    const float* w_input_proj = (const float*)d_in[7];
    const float* b_input_proj = (const float*)d_in[8];
    const float* w_in_proj    = (const float*)d_in[9];
    const float* conv_w       = (const float*)d_in[10];
    const float* conv_b       = (const float*)d_in[11];
    const float* A_log        = (const float*)d_in[12];
    const float* Dp           = (const float*)d_in[13];
    const float* dt_bias      = (const float*)d_in[14];
    const float* norm_w       = (const float*)d_in[15];
    const float* w_out_proj   = (const float*)d_in[16];
    const float* w_out_gate   = (const float*)d_in[17];
    const float* b_out_gate   = (const float*)d_in[18];
    const float* w_proj       = (const float*)d_in[19];
    const float* b_proj       = (const float*)d_in[20];

    float* out = (float*)d_out;
    float* out_clip = out;                                      // [1024, 512]
    float* out_conv = out + (size_t)BATCH * CLIP;               // [1024, 2560, 4]
    float* out_ssm  = out_conv + (size_t)BATCH * CONV_DIM * DC; // [1024, 32, 64, 64]

    float *x, *t1, *gated, *zx, *xbc, *yn, *outpre, *outf;
    cudaGetSymbolAddress((void**)&x,      g_x);
    cudaGetSymbolAddress((void**)&t1,     g_t1);
    cudaGetSymbolAddress((void**)&gated,  g_gated);
    cudaGetSymbolAddress((void**)&zx,     g_zx);
    cudaGetSymbolAddress((void**)&xbc,    g_xbc);
    cudaGetSymbolAddress((void**)&yn,     g_yn);
    cudaGetSymbolAddress((void**)&outpre, g_outpre);
    cudaGetSymbolAddress((void**)&outf,   g_outf);

    const int SMEM64  = (64  + 128) * 36 * 4 * 2;   // 55296
    const int SMEM128 = (128 + 128) * 36 * 4 * 2;   // 73728
    static bool attr_set = false;
    if (!attr_set) {
        cudaFuncSetAttribute(tf32_gemm<64>,  cudaFuncAttributeMaxDynamicSharedMemorySize, SMEM64);
        cudaFuncSetAttribute(tf32_gemm<128>, cudaFuncAttributeMaxDynamicSharedMemorySize, SMEM128);
        attr_set = true;
    }

    // 1. layernorm
    ln_kernel<<<BATCH, 256>>>(frame_feat, ln_w, ln_b, x);

    // 2. t1 = x @ w_input_proj^T + b
    tf32_gemm<64><<<dim3(HID / 128, BATCH / 64), 256, SMEM64>>>(
        x, w_input_proj, b_input_proj, nullptr, t1, BATCH, HID, IN_DIM, 0);

    // 3. gated = t1 * sigmoid(x @ w_in_gate^T + b)
    tf32_gemm<64><<<dim3(HID / 128, BATCH / 64), 256, SMEM64>>>(
        x, w_in_gate, b_in_gate, t1, gated, BATCH, HID, IN_DIM, 1);

    // 4. zxbcdt = gated @ w_in_proj^T
    tf32_gemm<128><<<dim3((DINP + 127) / 128, BATCH / 128), 256, SMEM128>>>(
        gated, w_in_proj, nullptr, nullptr, zx, BATCH, DINP, HID, 0);

    // 5. conv shift + depthwise conv + silu (writes new_conv output)
    conv_kernel<<<(BATCH * CONV_DIM + 255) / 256, 256>>>(conv_state, zx, conv_w, conv_b, out_conv, xbc);

    // 6. fused dt + SSM update + gate + group rmsnorm (writes new_ssm + yn)
    ssm_fused<<<BATCH * NG, 512>>>(ssm_state, zx, xbc, A_log, Dp, dt_bias, norm_w, out_ssm, yn);

    // 7. outpre = yn @ w_out_proj^T + gated
    tf32_gemm<64><<<dim3(HID / 128, BATCH / 64), 256, SMEM64>>>(
        yn, w_out_proj, nullptr, gated, outpre, BATCH, HID, DIN, 2);

    // 8. outf = outpre * sigmoid(outpre @ w_out_gate^T + b)
    tf32_gemm<64><<<dim3(HID / 128, BATCH / 64), 256, SMEM64>>>(
        outpre, w_out_gate, b_out_gate, outpre, outf, BATCH, HID, HID, 1);

    // 9. clip = outf @ w_proj^T + b
    tf32_gemm<64><<<dim3(CLIP / 128, BATCH / 64), 256, SMEM64>>>(
        outf, w_proj, b_proj, nullptr, out_clip, BATCH, CLIP, HID, 0);
}

// round 14
// speedup vs baseline: 2.1904x; 1.1086x over previous
#include <cuda_runtime.h>
#include <math.h>
#include <stdint.h>

#define IN_DIM   768
#define HID      1024
#define CLIP     512
#define NG       4
#define DS       64
#define DC       4
#define HD       64
#define DIN      2048
#define NH       32
#define CONV_DIM 2560
#define DINP     4640
#define BATCH    1024
#define EPS      1e-5f

// ---------------- scratch ----------------
__device__ float g_x[BATCH * IN_DIM];
__device__ float g_gated[BATCH * HID];
__device__ float g_zx[BATCH * DINP];
__device__ float g_xbc[BATCH * CONV_DIM];
__device__ float g_yn[BATCH * DIN];
__device__ float g_outpre[BATCH * HID];
__device__ float g_outf[BATCH * HID];

__device__ __forceinline__ float sigmoidf_(float v) { return 1.0f / (1.0f + expf(-v)); }
__device__ __forceinline__ float siluf_(float v)    { return v / (1.0f + expf(-v)); }

__device__ __forceinline__ unsigned f2tf32(float x) {
    unsigned r;
    asm("cvt.rna.tf32.f32 %0, %1;" : "=r"(r) : "f"(x));
    return r;
}

__device__ __forceinline__ void cp_async16(uint32_t dst, const void* src, int src_bytes) {
    asm volatile("cp.async.cg.shared.global [%0], [%1], 16, %2;\n"
                 :: "r"(dst), "l"(src), "r"(src_bytes));
}
__device__ __forceinline__ void cp_commit() {
    asm volatile("cp.async.commit_group;\n");
}
template<int N>
__device__ __forceinline__ void cp_wait() {
    asm volatile("cp.async.wait_group %0;\n" :: "n"(N));
}

// ---------------- layernorm ----------------
__global__ void ln_kernel(const float* __restrict__ ff,
                          const float* __restrict__ w,
                          const float* __restrict__ b,
                          float* __restrict__ out) {
    int row = blockIdx.x;
    const float* in = ff + (size_t)row * IN_DIM;
    float* o = out + (size_t)row * IN_DIM;
    int tid = threadIdx.x;               // 256 threads
    float v0 = in[tid], v1 = in[tid + 256], v2 = in[tid + 512];
    float s = v0 + v1 + v2;
    float s2 = v0 * v0 + v1 * v1 + v2 * v2;
    for (int o2 = 16; o2; o2 >>= 1) {
        s  += __shfl_down_sync(0xffffffffu, s,  o2);
        s2 += __shfl_down_sync(0xffffffffu, s2, o2);
    }
    __shared__ float ss[8], ss2[8];
    int wid = tid >> 5, lid = tid & 31;
    if (lid == 0) { ss[wid] = s; ss2[wid] = s2; }
    __syncthreads();
    __shared__ float mu_s, rstd_s;
    if (tid == 0) {
        float ts = 0.f, ts2 = 0.f;
        for (int i = 0; i < 8; i++) { ts += ss[i]; ts2 += ss2[i]; }
        float mu = ts / IN_DIM;
        float var = ts2 / IN_DIM - mu * mu;
        mu_s = mu;
        rstd_s = rsqrtf(var + EPS);
    }
    __syncthreads();
    float mu = mu_s, rstd = rstd_s;
    o[tid]       = (v0 - mu) * rstd * w[tid]       + b[tid];
    o[tid + 256] = (v1 - mu) * rstd * w[tid + 256] + b[tid + 256];
    o[tid + 512] = (v2 - mu) * rstd * w[tid + 512] + b[tid + 512];
}

// ---------------- TF32 tensor-core GEMM, cp.async double-buffered ----------------
// C[M,N] = A[M,K] @ W[N,K]^T (+ bias), epilogue modes:
//   0: C = acc(+bias)   1: C = other * sigmoid(acc(+bias))   2: C = acc + other
// Block BM x 128, BK=32, 256 threads (8 warps 2x4), warp tile (BM/2) x 32.
template<int BM>
__global__ __launch_bounds__(256, 2)
void tf32_gemm(const float* __restrict__ A, const float* __restrict__ W,
               const float* __restrict__ bias, const float* __restrict__ other,
               float* __restrict__ C, int M, int N, int K, int mode)
{
    constexpr int BN = 128;
    constexpr int BK = 32;
    constexpr int MT = BM / 32;
    constexpr int PITCH = 36;
    constexpr int STAGE = (BM + BN) * PITCH;

    extern __shared__ float smem[];

    int tid  = threadIdx.x;
    int warp = tid >> 5, lane = tid & 31;
    int g    = lane >> 2, tig = lane & 3;
    int wm   = (warp >> 2) * (MT * 16);
    int wn   = (warp & 3) * 32;
    int m0   = blockIdx.y * BM;
    int n0   = blockIdx.x * BN;

    int lrow = tid >> 3;          // 0..31
    int lcol = (tid & 7) * 4;     // 0,4,...,28

    float acc[MT][4][4];
#pragma unroll
    for (int i = 0; i < MT; i++)
#pragma unroll
        for (int j = 0; j < 4; j++)
#pragma unroll
            for (int c = 0; c < 4; c++) acc[i][j][c] = 0.f;

    const int niter = K / BK;

    auto issue = [&](int it, int buf) {
        int k0 = it * BK;
        float* sa = smem + buf * STAGE;
        float* sb = sa + BM * PITCH;
#pragma unroll
        for (int p = 0; p < BM / 32; p++) {
            int r = p * 32 + lrow;
            uint32_t dst = (uint32_t)__cvta_generic_to_shared(sa + r * PITCH + lcol);
            cp_async16(dst, A + (size_t)(m0 + r) * K + k0 + lcol, 16);
        }
#pragma unroll
        for (int p = 0; p < 4; p++) {
            int r = p * 32 + lrow;
            int gn = n0 + r;
            uint32_t dst = (uint32_t)__cvta_generic_to_shared(sb + r * PITCH + lcol);
            const float* src = W + (size_t)(gn < N ? gn : (N - 1)) * K + k0 + lcol;
            cp_async16(dst, src, gn < N ? 16 : 0);
        }
    };

    issue(0, 0);
    cp_commit();

    for (int it = 0; it < niter; ++it) {
        int buf = it & 1;
        if (it + 1 < niter) {
            issue(it + 1, buf ^ 1);
            cp_commit();
            cp_wait<1>();
        } else {
            cp_wait<0>();
        }
        __syncthreads();

        const float* sa = smem + buf * STAGE;
        const float* sb = sa + BM * PITCH;

#pragma unroll
        for (int k8 = 0; k8 < 4; k8++) {
            int kb = k8 * 8;
            unsigned a[MT][4], b[4][2];
#pragma unroll
            for (int mt = 0; mt < MT; mt++) {
                int m = wm + mt * 16;
                a[mt][0] = f2tf32(sa[(m + g) * PITCH + kb + tig]);
                a[mt][1] = f2tf32(sa[(m + g + 8) * PITCH + kb + tig]);
                a[mt][2] = f2tf32(sa[(m + g) * PITCH + kb + tig + 4]);
                a[mt][3] = f2tf32(sa[(m + g + 8) * PITCH + kb + tig + 4]);
            }
#pragma unroll
            for (int nt = 0; nt < 4; nt++) {
                int n = wn + nt * 8;
                b[nt][0] = f2tf32(sb[(n + g) * PITCH + kb + tig]);
                b[nt][1] = f2tf32(sb[(n + g) * PITCH + kb + tig + 4]);
            }
#pragma unroll
            for (int mt = 0; mt < MT; mt++)
#pragma unroll
                for (int nt = 0; nt < 4; nt++) {
                    asm volatile(
                        "mma.sync.aligned.m16n8k8.row.col.f32.tf32.tf32.f32 "
                        "{%0,%1,%2,%3}, {%4,%5,%6,%7}, {%8,%9}, {%0,%1,%2,%3};\n"
                        : "+f"(acc[mt][nt][0]), "+f"(acc[mt][nt][1]),
                          "+f"(acc[mt][nt][2]), "+f"(acc[mt][nt][3])
                        : "r"(a[mt][0]), "r"(a[mt][1]), "r"(a[mt][2]), "r"(a[mt][3]),
                          "r"(b[nt][0]), "r"(b[nt][1]));
                }
        }
        __syncthreads();
    }

    // epilogue
#pragma unroll
    for (int mt = 0; mt < MT; mt++) {
#pragma unroll
        for (int nt = 0; nt < 4; nt++) {
            int ng = n0 + wn + nt * 8 + 2 * tig;
            if (ng >= N) continue;
#pragma unroll
            for (int half = 0; half < 2; half++) {
                int mg = m0 + wm + mt * 16 + g + half * 8;
                float v0 = acc[mt][nt][half * 2 + 0];
                float v1 = acc[mt][nt][half * 2 + 1];
                if (bias) { v0 += bias[ng]; v1 += bias[ng + 1]; }
                size_t off = (size_t)mg * N + ng;
                if (mode == 1) {
                    v0 = other[off]     * sigmoidf_(v0);
                    v1 = other[off + 1] * sigmoidf_(v1);
                } else if (mode == 2) {
                    v0 += other[off];
                    v1 += other[off + 1];
                }
                *(float2*)(C + off) = make_float2(v0, v1);
            }
        }
    }
}

// ---------------- dual TF32 GEMM: gated = (A@W1^T+b1) * sigmoid(A@W2^T+b2) ----------------
// Fixed shapes: M=1024, N=1024, K=768.  BM=64, BN=128, shared A tile, two B tiles.
__global__ __launch_bounds__(256, 2)
void tf32_dual_gemm(const float* __restrict__ A,
                    const float* __restrict__ W1, const float* __restrict__ b1,
                    const float* __restrict__ W2, const float* __restrict__ b2,
                    float* __restrict__ C)
{
    constexpr int BM = 64, BN = 128, BK = 32, MT = 2;
    constexpr int PITCH = 36;
    constexpr int STAGE = (BM + 2 * BN) * PITCH;
    const int N = HID, K = IN_DIM;

    extern __shared__ float smem[];

    int tid  = threadIdx.x;
    int warp = tid >> 5, lane = tid & 31;
    int g    = lane >> 2, tig = lane & 3;
    int wm   = (warp >> 2) * (MT * 16);
    int wn   = (warp & 3) * 32;
    int m0   = blockIdx.y * BM;
    int n0   = blockIdx.x * BN;

    int lrow = tid >> 3;
    int lcol = (tid & 7) * 4;

    float acc1[MT][4][4], acc2[MT][4][4];
#pragma unroll
    for (int i = 0; i < MT; i++)
#pragma unroll
        for (int j = 0; j < 4; j++)
#pragma unroll
            for (int c = 0; c < 4; c++) { acc1[i][j][c] = 0.f; acc2[i][j][c] = 0.f; }

    const int niter = K / BK;

    auto issue = [&](int it, int buf) {
        int k0 = it * BK;
        float* sa  = smem + buf * STAGE;
        float* sb1 = sa + BM * PITCH;
        float* sb2 = sb1 + BN * PITCH;
#pragma unroll
        for (int p = 0; p < 2; p++) {
            int r = p * 32 + lrow;
            uint32_t dst = (uint32_t)__cvta_generic_to_shared(sa + r * PITCH + lcol);
            cp_async16(dst, A + (size_t)(m0 + r) * K + k0 + lcol, 16);
        }
#pragma unroll
        for (int p = 0; p < 4; p++) {
            int r = p * 32 + lrow;
            uint32_t d1 = (uint32_t)__cvta_generic_to_shared(sb1 + r * PITCH + lcol);
            cp_async16(d1, W1 + (size_t)(n0 + r) * K + k0 + lcol, 16);
            uint32_t d2 = (uint32_t)__cvta_generic_to_shared(sb2 + r * PITCH + lcol);
            cp_async16(d2, W2 + (size_t)(n0 + r) * K + k0 + lcol, 16);
        }
    };

    issue(0, 0);
    cp_commit();

    for (int it = 0; it < niter; ++it) {
        int buf = it & 1;
        if (it + 1 < niter) {
            issue(it + 1, buf ^ 1);
            cp_commit();
            cp_wait<1>();
        } else {
            cp_wait<0>();
        }
        __syncthreads();

        const float* sa  = smem + buf * STAGE;
        const float* sb1 = sa + BM * PITCH;
        const float* sb2 = sb1 + BN * PITCH;

#pragma unroll
        for (int k8 = 0; k8 < 4; k8++) {
            int kb = k8 * 8;
            unsigned a[MT][4];
#pragma unroll
            for (int mt = 0; mt < MT; mt++) {
                int m = wm + mt * 16;
                a[mt][0] = f2tf32(sa[(m + g) * PITCH + kb + tig]);
                a[mt][1] = f2tf32(sa[(m + g + 8) * PITCH + kb + tig]);
                a[mt][2] = f2tf32(sa[(m + g) * PITCH + kb + tig + 4]);
                a[mt][3] = f2tf32(sa[(m + g + 8) * PITCH + kb + tig + 4]);
            }
#pragma unroll
            for (int nt = 0; nt < 4; nt++) {
                int n = wn + nt * 8;
                unsigned p0 = f2tf32(sb1[(n + g) * PITCH + kb + tig]);
                unsigned p1 = f2tf32(sb1[(n + g) * PITCH + kb + tig + 4]);
                unsigned q0 = f2tf32(sb2[(n + g) * PITCH + kb + tig]);
                unsigned q1 = f2tf32(sb2[(n + g) * PITCH + kb + tig + 4]);
#pragma unroll
                for (int mt = 0; mt < MT; mt++) {
                    asm volatile(
                        "mma.sync.aligned.m16n8k8.row.col.f32.tf32.tf32.f32 "
                        "{%0,%1,%2,%3}, {%4,%5,%6,%7}, {%8,%9}, {%0,%1,%2,%3};\n"
                        : "+f"(acc1[mt][nt][0]), "+f"(acc1[mt][nt][1]),
                          "+f"(acc1[mt][nt][2]), "+f"(acc1[mt][nt][3])
                        : "r"(a[mt][0]), "r"(a[mt][1]), "r"(a[mt][2]), "r"(a[mt][3]),
                          "r"(p0), "r"(p1));
                    asm volatile(
                        "mma.sync.aligned.m16n8k8.row.col.f32.tf32.tf32.f32 "
                        "{%0,%1,%2,%3}, {%4,%5,%6,%7}, {%8,%9}, {%0,%1,%2,%3};\n"
                        : "+f"(acc2[mt][nt][0]), "+f"(acc2[mt][nt][1]),
                          "+f"(acc2[mt][nt][2]), "+f"(acc2[mt][nt][3])
                        : "r"(a[mt][0]), "r"(a[mt][1]), "r"(a[mt][2]), "r"(a[mt][3]),
                          "r"(q0), "r"(q1));
                }
            }
        }
        __syncthreads();
    }

#pragma unroll
    for (int mt = 0; mt < MT; mt++) {
#pragma unroll
        for (int nt = 0; nt < 4; nt++) {
            int ng = n0 + wn + nt * 8 + 2 * tig;
#pragma unroll
            for (int half = 0; half < 2; half++) {
                int mg = m0 + wm + mt * 16 + g + half * 8;
                float u0 = acc1[mt][nt][half * 2 + 0] + b1[ng];
                float u1 = acc1[mt][nt][half * 2 + 1] + b1[ng + 1];
                float v0 = acc2[mt][nt][half * 2 + 0] + b2[ng];
                float v1 = acc2[mt][nt][half * 2 + 1] + b2[ng + 1];
                size_t off = (size_t)mg * N + ng;
                *(float2*)(C + off) = make_float2(u0 * sigmoidf_(v0), u1 * sigmoidf_(v1));
            }
        }
    }
}

// ---------------- conv shift + depthwise conv + silu ----------------
__global__ void conv_kernel(const float* __restrict__ conv_state,
                            const float* __restrict__ zx,
                            const float* __restrict__ conv_w,
                            const float* __restrict__ conv_b,
                            float* __restrict__ new_conv_out,
                            float* __restrict__ xbc_act) {
    int idx = blockIdx.x * blockDim.x + threadIdx.x;   // b*CONV_DIM + c
    if (idx >= BATCH * CONV_DIM) return;
    int b = idx / CONV_DIM, c = idx - b * CONV_DIM;
    float4 cs = ((const float4*)conv_state)[idx];
    float xn = zx[(size_t)b * DINP + DIN + c];
    float4 w = ((const float4*)conv_w)[c];
    float acc = cs.y * w.x + cs.z * w.y + cs.w * w.z + xn * w.w + conv_b[c];
    xbc_act[idx] = siluf_(acc);
    ((float4*)new_conv_out)[idx] = make_float4(cs.y, cs.z, cs.w, xn);
}

// ---------------- fused: dt + SSM update + gate + group RMS norm ----------------
__global__ __launch_bounds__(512)
void ssm_fused(const float* __restrict__ ssm_state,
               const float* __restrict__ zx,
               const float* __restrict__ xbc,
               const float* __restrict__ A_log,
               const float* __restrict__ Dp,
               const float* __restrict__ dt_bias,
               const float* __restrict__ norm_w,
               float* __restrict__ new_ssm_out,
               float* __restrict__ yn) {
    int bg = blockIdx.x;
    int b = bg >> 2, g = bg & 3;
    int tid = threadIdx.x;
    int h_loc = tid >> 6;
    int t64 = tid & 63;
    int tn = t64 & 15;
    int pg = t64 >> 4;
    int h = g * 8 + h_loc;

    __shared__ float Bsh[DS], Csh[DS], Xsh[512], Zsh[512], Yv[512];
    __shared__ float dtsh[8], dAsh[8], Dpsh[8];

    if (tid < DS)
        Bsh[tid] = xbc[(size_t)b * CONV_DIM + DIN + g * DS + tid];
    else if (tid < 2 * DS)
        Csh[tid - DS] = xbc[(size_t)b * CONV_DIM + DIN + NG * DS + g * DS + (tid - DS)];
    Xsh[tid] = xbc[(size_t)b * CONV_DIM + g * 512 + tid];
    Zsh[tid] = zx[(size_t)b * DINP + g * 512 + tid];
    if (tid < 8) {
        int hh = g * 8 + tid;
        float raw = zx[(size_t)b * DINP + DIN + CONV_DIM + hh] + dt_bias[hh];
        float sp = (raw > 20.f) ? raw : log1pf(expf(raw));
        dtsh[tid] = sp;
        dAsh[tid] = expf(sp * -expf(A_log[hh]));
        Dpsh[tid] = Dp[hh];
    }
    __syncthreads();

    float4 B4 = *(const float4*)&Bsh[tn * 4];
    float4 C4 = *(const float4*)&Csh[tn * 4];
    float dtv = dtsh[h_loc], dAv = dAsh[h_loc];

    size_t head_base = (((size_t)b * NH + h) * HD) * DS;

    float part[16];
#pragma unroll
    for (int i = 0; i < 16; i++) {
        int p = pg * 16 + i;
        size_t off = head_base + (size_t)p * DS + tn * 4;
        float4 s = *(const float4*)(ssm_state + off);
        float coef = dtv * Xsh[h_loc * 64 + p];
        float4 ns;
        ns.x = fmaf(s.x, dAv, coef * B4.x);
        ns.y = fmaf(s.y, dAv, coef * B4.y);
        ns.z = fmaf(s.z, dAv, coef * B4.z);
        ns.w = fmaf(s.w, dAv, coef * B4.w);
        *(float4*)(new_ssm_out + off) = ns;
        part[i] = ns.x * C4.x + ns.y * C4.y + ns.z * C4.z + ns.w * C4.w;
    }

#pragma unroll
    for (int i = 0; i < 16; i++) {
        float v = part[i];
        v += __shfl_down_sync(0xffffffffu, v, 8, 16);
        v += __shfl_down_sync(0xffffffffu, v, 4, 16);
        v += __shfl_down_sync(0xffffffffu, v, 2, 16);
        v += __shfl_down_sync(0xffffffffu, v, 1, 16);
        part[i] = v;
    }
    if (tn == 0) {
        float dp = Dpsh[h_loc];
#pragma unroll
        for (int i = 0; i < 16; i++) {
            int p = pg * 16 + i;
            float x = Xsh[h_loc * 64 + p];
            float y = part[i] + dp * x;
            float z = Zsh[h_loc * 64 + p];
            Yv[h_loc * 64 + p] = y * siluf_(z);
        }
    }
    __syncthreads();

    float v = Yv[tid];
    float ss = v * v;
    for (int o = 16; o; o >>= 1) ss += __shfl_down_sync(0xffffffffu, ss, o);
    __shared__ float wsums[16];
    int wid = tid >> 5, lid = tid & 31;
    if (lid == 0) wsums[wid] = ss;
    __syncthreads();
    __shared__ float scale_s;
    if (tid == 0) {
        float tot = 0.f;
        for (int i = 0; i < 16; i++) tot += wsums[i];
        scale_s = rsqrtf(tot / 512.f + EPS);
    }
    __syncthreads();
    yn[(size_t)b * DIN + g * 512 + tid] = v * scale_s * norm_w[g * 512 + tid];
}

// ---------------- launch ----------------
extern "C" void kernel_launch(void* const* d_in, const int* in_sizes, int n_in,
                              void* d_out, int out_size) {
    const float* frame_feat   = (const float*)d_in[0];
    const float* conv_state   = (const float*)d_in[1];
    const float* ssm_state    = (const float*)d_in[2];
    const float* ln_w         = (const float*)d_in[3];
    const float* ln_b         = (const float*)d_in[4];
    const float* w_in_gate    = (const float*)d_in[5];
    const float* b_in_gate    = (const float*)d_in[6];
    const float* w_input_proj = (const float*)d_in[7];
    const float* b_input_proj = (const float*)d_in[8];
    const float* w_in_proj    = (const float*)d_in[9];
    const float* conv_w       = (const float*)d_in[10];
    const float* conv_b       = (const float*)d_in[11];
    const float* A_log        = (const float*)d_in[12];
    const float* Dp           = (const float*)d_in[13];
    const float* dt_bias      = (const float*)d_in[14];
    const float* norm_w       = (const float*)d_in[15];
    const float* w_out_proj   = (const float*)d_in[16];
    const float* w_out_gate   = (const float*)d_in[17];
    const float* b_out_gate   = (const float*)d_in[18];
    const float* w_proj       = (const float*)d_in[19];
    const float* b_proj       = (const float*)d_in[20];

    float* out = (float*)d_out;
    float* out_clip = out;                                      // [1024, 512]
    float* out_conv = out + (size_t)BATCH * CLIP;               // [1024, 2560, 4]
    float* out_ssm  = out_conv + (size_t)BATCH * CONV_DIM * DC; // [1024, 32, 64, 64]

    float *x, *gated, *zx, *xbc, *yn, *outpre, *outf;
    cudaGetSymbolAddress((void**)&x,      g_x);
    cudaGetSymbolAddress((void**)&gated,  g_gated);
    cudaGetSymbolAddress((void**)&zx,     g_zx);
    cudaGetSymbolAddress((void**)&xbc,    g_xbc);
    cudaGetSymbolAddress((void**)&yn,     g_yn);
    cudaGetSymbolAddress((void**)&outpre, g_outpre);
    cudaGetSymbolAddress((void**)&outf,   g_outf);

    const int SMEM64   = (64  + 128) * 36 * 4 * 2;       // 55296
    const int SMEM128  = (128 + 128) * 36 * 4 * 2;       // 73728
    const int SMEMDUAL = (64 + 256) * 36 * 4 * 2;        // 92160
    static bool attr_set = false;
    if (!attr_set) {
        cudaFuncSetAttribute(tf32_gemm<64>,  cudaFuncAttributeMaxDynamicSharedMemorySize, SMEM64);
        cudaFuncSetAttribute(tf32_gemm<128>, cudaFuncAttributeMaxDynamicSharedMemorySize, SMEM128);
        cudaFuncSetAttribute(tf32_dual_gemm, cudaFuncAttributeMaxDynamicSharedMemorySize, SMEMDUAL);
        attr_set = true;
    }

    // 1. layernorm
    ln_kernel<<<BATCH, 256>>>(frame_feat, ln_w, ln_b, x);

    // 2. gated = (x@w_input_proj^T+b) * sigmoid(x@w_in_gate^T+b)   (dual fused)
    tf32_dual_gemm<<<dim3(HID / 128, BATCH / 64), 256, SMEMDUAL>>>(
        x, w_input_proj, b_input_proj, w_in_gate, b_in_gate, gated);

    // 3. zxbcdt = gated @ w_in_proj^T
    tf32_gemm<128><<<dim3((DINP + 127) / 128, BATCH / 128), 256, SMEM128>>>(
        gated, w_in_proj, nullptr, nullptr, zx, BATCH, DINP, HID, 0);

    // 4. conv shift + depthwise conv + silu (writes new_conv output)
    conv_kernel<<<(BATCH * CONV_DIM + 255) / 256, 256>>>(conv_state, zx, conv_w, conv_b, out_conv, xbc);

    // 5. fused dt + SSM update + gate + group rmsnorm (writes new_ssm + yn)
    ssm_fused<<<BATCH * NG, 512>>>(ssm_state, zx, xbc, A_log, Dp, dt_bias, norm_w, out_ssm, yn);

    // 6. outpre = yn @ w_out_proj^T + gated
    tf32_gemm<64><<<dim3(HID / 128, BATCH / 64), 256, SMEM64>>>(
        yn, w_out_proj, nullptr, gated, outpre, BATCH, HID, DIN, 2);

    // 7. outf = outpre * sigmoid(outpre @ w_out_gate^T + b)
    tf32_gemm<64><<<dim3(HID / 128, BATCH / 64), 256, SMEM64>>>(
        outpre, w_out_gate, b_out_gate, outpre, outf, BATCH, HID, HID, 1);

    // 8. clip = outf @ w_proj^T + b
    tf32_gemm<64><<<dim3(CLIP / 128, BATCH / 64), 256, SMEM64>>>(
        outf, w_proj, b_proj, nullptr, out_clip, BATCH, CLIP, HID, 0);
}